// round 2
// baseline (speedup 1.0000x reference)
#include <cuda_runtime.h>
#include <math.h>

#define FEAT  512
#define NCLS  100000
#define NROW  512
#define BM    128
#define BN    128
#define BK    16
#define CT    782      // ceil(100000/128)
#define RT    4        // 512/128

#define C_COS_M   0.87758256189037276f
#define C_SIN_M   0.47942553860420301f
#define C_THRESH  (-0.87758256189037276f)
#define C_MM      0.23971276930210156f
#define C_S       64.0f
#define C_EPS     0.1f

// ---- scratch (static device globals; no runtime allocation) ----
__device__ float g_e[NROW * FEAT];     // normalized embeddings
__device__ float g_invwn[NCLS];        // 1/||w_col||
__device__ float g_ctm[NROW];          // cos(theta+m) per row
__device__ float g_ft[NROW];           // final target logit (cos units)
__device__ float g_t;                  // adaptive t
__device__ float g_pm[NROW * CT];      // per (row, class-tile) partial max
__device__ float g_ps[NROW * CT];      // partial sum exp
__device__ float g_psl[NROW * CT];     // partial sum of logits
__device__ float g_rowloss[NROW];

// ---------------------------------------------------------------
// K1: row-normalize embeddings -> g_e
// ---------------------------------------------------------------
__global__ void k_norm_e(const float* __restrict__ emb) {
    int r = blockIdx.x;          // 512 blocks
    int t = threadIdx.x;         // 128 threads
    float v[4], s = 0.f;
#pragma unroll
    for (int i = 0; i < 4; i++) {
        v[i] = emb[r * FEAT + t + i * 128];
        s += v[i] * v[i];
    }
#pragma unroll
    for (int o = 16; o; o >>= 1) s += __shfl_xor_sync(0xffffffffu, s, o);
    __shared__ float sm[4];
    if ((t & 31) == 0) sm[t >> 5] = s;
    __syncthreads();
    float inv = 1.0f / sqrtf(sm[0] + sm[1] + sm[2] + sm[3]);
#pragma unroll
    for (int i = 0; i < 4; i++)
        g_e[r * FEAT + t + i * 128] = v[i] * inv;
}

// ---------------------------------------------------------------
// K2: column inverse norms of w -> g_invwn
// ---------------------------------------------------------------
__global__ void k_invwn(const float* __restrict__ w) {
    int c = blockIdx.x * 256 + threadIdx.x;
    if (c >= NCLS) return;
    float s = 0.f;
#pragma unroll 8
    for (int k = 0; k < FEAT; k++) {
        float v = w[k * NCLS + c];
        s += v * v;
    }
    g_invwn[c] = 1.0f / sqrtf(s);
}

// ---------------------------------------------------------------
// K3: target logits, cos_theta_m, final_target, t
// ---------------------------------------------------------------
__global__ void k_target(const float* __restrict__ w, const int* __restrict__ label) {
    int i = threadIdx.x;                 // 512 threads, 1 block
    int lab = label[i];
    const float* e = g_e + i * FEAT;
    float dot = 0.f;
#pragma unroll 8
    for (int k = 0; k < FEAT; k++)
        dot += e[k] * w[k * NCLS + lab];
    float tl = fminf(1.0f, fmaxf(-1.0f, dot * g_invwn[lab]));
    float sint = sqrtf(fmaxf(0.f, 1.0f - tl * tl));
    float ctm  = tl * C_COS_M - sint * C_SIN_M;
    g_ctm[i] = ctm;
    g_ft[i]  = (tl > C_THRESH) ? ctm : (tl - C_MM);

    // mean(target_logit) -> t
    float s = tl;
#pragma unroll
    for (int o = 16; o; o >>= 1) s += __shfl_xor_sync(0xffffffffu, s, o);
    __shared__ float sm[16];
    if ((i & 31) == 0) sm[i >> 5] = s;
    __syncthreads();
    if (i < 16) {
        float v = sm[i];
#pragma unroll
        for (int o = 8; o; o >>= 1) v += __shfl_xor_sync(0x0000ffffu, v, o);
        if (i == 0) g_t = 0.01f * (v / (float)NROW);
    }
}

// ---------------------------------------------------------------
// K4: fused GEMM (e @ w, scaled) + CurricularFace transform +
//     per (row, class-tile) online-softmax partials
// ---------------------------------------------------------------
__global__ void __launch_bounds__(256, 2)
k_main(const float* __restrict__ w, const int* __restrict__ label) {
    const int rtile = blockIdx.x;     // 0..3   (fast dim -> wave shares w slice)
    const int ct    = blockIdx.y;     // 0..781
    const int c0 = ct * BN;
    const int r0 = rtile * BM;
    const int tid = threadIdx.x;
    const int tr = tid >> 4;          // 0..15 -> rows tr*8..tr*8+7
    const int tc = tid & 15;          // 0..15 -> cols tc*8..tc*8+7

    __shared__ float As[BK][BM];
    __shared__ float Bs[BK][BN];

    float acc[8][8];
#pragma unroll
    for (int i = 0; i < 8; i++)
#pragma unroll
        for (int j = 0; j < 8; j++) acc[i][j] = 0.f;

    // load-vector assignments (2 float4 per thread per operand)
    int a_row[2], a_kv[2], b_kr[2], b_cv[2];
    a_row[0] = tid >> 2;          a_kv[0] = tid & 3;
    a_row[1] = (tid + 256) >> 2;  a_kv[1] = (tid + 256) & 3;
    b_kr[0] = tid >> 5;           b_cv[0] = tid & 31;
    b_kr[1] = (tid + 256) >> 5;   b_cv[1] = (tid + 256) & 31;

    const float* eptr = g_e + r0 * FEAT;
    float4 ra[2], rb[2];

    // prologue loads (kt = 0)
#pragma unroll
    for (int u = 0; u < 2; u++) {
        ra[u] = *(const float4*)(eptr + a_row[u] * FEAT + a_kv[u] * 4);
        int col  = c0 + b_cv[u] * 4;
        int krow = b_kr[u];
        if (col + 3 < NCLS) {
            rb[u] = *(const float4*)(w + krow * NCLS + col);
        } else {
            rb[u].x = (col + 0 < NCLS) ? w[krow * NCLS + col + 0] : 0.f;
            rb[u].y = (col + 1 < NCLS) ? w[krow * NCLS + col + 1] : 0.f;
            rb[u].z = (col + 2 < NCLS) ? w[krow * NCLS + col + 2] : 0.f;
            rb[u].w = (col + 3 < NCLS) ? w[krow * NCLS + col + 3] : 0.f;
        }
    }

    for (int kt = 0; kt < FEAT / BK; kt++) {
        // commit current regs to smem
#pragma unroll
        for (int u = 0; u < 2; u++) {
            int kb = a_kv[u] * 4;
            As[kb + 0][a_row[u]] = ra[u].x;
            As[kb + 1][a_row[u]] = ra[u].y;
            As[kb + 2][a_row[u]] = ra[u].z;
            As[kb + 3][a_row[u]] = ra[u].w;
            *(float4*)&Bs[b_kr[u]][b_cv[u] * 4] = rb[u];
        }
        __syncthreads();

        // prefetch next tile
        if (kt + 1 < FEAT / BK) {
            int k0 = (kt + 1) * BK;
#pragma unroll
            for (int u = 0; u < 2; u++) {
                ra[u] = *(const float4*)(eptr + a_row[u] * FEAT + k0 + a_kv[u] * 4);
                int col  = c0 + b_cv[u] * 4;
                int krow = k0 + b_kr[u];
                if (col + 3 < NCLS) {
                    rb[u] = *(const float4*)(w + krow * NCLS + col);
                } else {
                    rb[u].x = (col + 0 < NCLS) ? w[krow * NCLS + col + 0] : 0.f;
                    rb[u].y = (col + 1 < NCLS) ? w[krow * NCLS + col + 1] : 0.f;
                    rb[u].z = (col + 2 < NCLS) ? w[krow * NCLS + col + 2] : 0.f;
                    rb[u].w = (col + 3 < NCLS) ? w[krow * NCLS + col + 3] : 0.f;
                }
            }
        }

        // compute
#pragma unroll
        for (int kk = 0; kk < BK; kk++) {
            float a[8], b[8];
#pragma unroll
            for (int i = 0; i < 8; i++) a[i] = As[kk][tr * 8 + i];
#pragma unroll
            for (int j = 0; j < 8; j++) b[j] = Bs[kk][tc * 8 + j];
#pragma unroll
            for (int i = 0; i < 8; i++)
#pragma unroll
                for (int j = 0; j < 8; j++)
                    acc[i][j] += a[i] * b[j];
        }
        __syncthreads();
    }

    // ---- epilogue: transform + per-row online softmax partials ----
    const float t_adapt = g_t;
#pragma unroll
    for (int i = 0; i < 8; i++) {
        int r = r0 + tr * 8 + i;
        float ctm = g_ctm[r];
        float ft  = g_ft[r];
        int lab   = label[r];

        float lmax = -3.0e38f;
#pragma unroll
        for (int j = 0; j < 8; j++) {
            int c = c0 + tc * 8 + j;
            float logit;
            if (c < NCLS) {
                float cosv = acc[i][j] * g_invwn[c];
                cosv = fminf(1.f, fmaxf(-1.f, cosv));
                if (c == lab) {
                    logit = C_S * ft;
                } else {
                    if (cosv > ctm) cosv = cosv * (t_adapt + cosv);
                    logit = C_S * cosv;
                }
                lmax = fmaxf(lmax, logit);
            } else {
                logit = -3.0e38f;
            }
            acc[i][j] = logit;
        }
#pragma unroll
        for (int o = 8; o; o >>= 1)
            lmax = fmaxf(lmax, __shfl_xor_sync(0xffffffffu, lmax, o, 16));

        float s = 0.f, sl = 0.f;
#pragma unroll
        for (int j = 0; j < 8; j++) {
            int c = c0 + tc * 8 + j;
            if (c < NCLS) {
                s  += expf(acc[i][j] - lmax);
                sl += acc[i][j];
            }
        }
#pragma unroll
        for (int o = 8; o; o >>= 1) {
            s  += __shfl_xor_sync(0xffffffffu, s,  o, 16);
            sl += __shfl_xor_sync(0xffffffffu, sl, o, 16);
        }
        if (tc == 0) {
            g_pm[r * CT + ct]  = lmax;
            g_ps[r * CT + ct]  = s;
            g_psl[r * CT + ct] = sl;
        }
    }
}

// ---------------------------------------------------------------
// K5: merge per-tile partials per row -> per-row loss
// ---------------------------------------------------------------
__global__ void k_rowreduce() {
    int r = blockIdx.x;          // 512 blocks
    int tid = threadIdx.x;       // 256 threads
    float m = -3.0e38f, s = 0.f, sl = 0.f;
    for (int ct = tid; ct < CT; ct += 256) {
        float m2 = g_pm[r * CT + ct];
        float s2 = g_ps[r * CT + ct];
        sl += g_psl[r * CT + ct];
        if (m2 > m) { s = s * expf(m - m2) + s2; m = m2; }
        else        { s += s2 * expf(m2 - m); }
    }
    __shared__ float sm_m[256], sm_s[256], sm_sl[256];
    sm_m[tid] = m; sm_s[tid] = s; sm_sl[tid] = sl;
    __syncthreads();
    for (int o = 128; o; o >>= 1) {
        if (tid < o) {
            float m1 = sm_m[tid], s1 = sm_s[tid];
            float m2 = sm_m[tid + o], s2 = sm_s[tid + o];
            float M = fmaxf(m1, m2);
            sm_s[tid] = s1 * expf(m1 - M) + s2 * expf(m2 - M);
            sm_m[tid] = M;
            sm_sl[tid] += sm_sl[tid + o];
        }
        __syncthreads();
    }
    if (tid == 0) {
        float LSE = sm_m[0] + logf(sm_s[0]);
        float nll    = LSE - C_S * g_ft[r];
        float smooth = LSE - sm_sl[0] / (float)NCLS;
        g_rowloss[r] = (1.0f - C_EPS) * nll + C_EPS * smooth;
    }
}

// ---------------------------------------------------------------
// K6: mean over rows -> scalar loss
// ---------------------------------------------------------------
__global__ void k_final(float* __restrict__ out) {
    int tid = threadIdx.x;       // 512 threads, 1 block
    float v = g_rowloss[tid];
#pragma unroll
    for (int o = 16; o; o >>= 1) v += __shfl_xor_sync(0xffffffffu, v, o);
    __shared__ float sm[16];
    if ((tid & 31) == 0) sm[tid >> 5] = v;
    __syncthreads();
    if (tid < 16) {
        float x = sm[tid];
#pragma unroll
        for (int o = 8; o; o >>= 1) x += __shfl_xor_sync(0x0000ffffu, x, o);
        if (tid == 0) out[0] = x / (float)NROW;
    }
}

// ---------------------------------------------------------------
extern "C" void kernel_launch(void* const* d_in, const int* in_sizes, int n_in,
                              void* d_out, int out_size) {
    const float* emb   = (const float*)d_in[0];
    const float* w     = (const float*)d_in[1];
    const int*   label = (const int*)d_in[2];
    float* out = (float*)d_out;

    k_norm_e<<<NROW, 128>>>(emb);
    k_invwn<<<(NCLS + 255) / 256, 256>>>(w);
    k_target<<<1, NROW>>>(w, label);
    k_main<<<dim3(RT, CT), 256>>>(w, label);
    k_rowreduce<<<NROW, 256>>>();
    k_final<<<1, NROW>>>(out);
}

// round 6
// speedup vs baseline: 5.7282x; 5.7282x over previous
#include <cuda_runtime.h>
#include <cuda_bf16.h>
#include <stdint.h>
#include <math.h>

#define FEAT  512
#define NCLS  100000
#define NROW  512
#define CPAD  100096          // 782*128 padded classes
#define BM    128
#define BN    128
#define NCT   782             // class tiles
#define NRT   4               // row tiles
#define CTP   782             // one partial per (row, class tile)
#define NCH   8               // K chunks of 64

#define C_COS_M   0.87758256189037276f
#define C_SIN_M   0.47942553860420301f
#define C_THRESH  (-0.87758256189037276f)
#define C_MM      0.23971276930210156f
#define C_S       64.0f
#define C_EPS     0.1f

// ---- scratch ----
__device__ float          g_e[NROW * FEAT];
__device__ __nv_bfloat16  g_ebf[NROW * FEAT];
__device__ __nv_bfloat16  g_wbf[(size_t)CPAD * FEAT];   // w^T bf16 K-major
__device__ float g_invwn[NCLS];
__device__ float g_tl[NROW];
__device__ float g_ctm[NROW];
__device__ float g_ft[NROW];
__device__ float g_t;
__device__ float g_pm[NROW * CTP];
__device__ float g_ps[NROW * CTP];
__device__ float g_psl[NROW * CTP];
__device__ float g_rowloss[NROW];

// =================== helpers ===================
__device__ __forceinline__ void cp16(uint32_t dst, const void* src) {
    asm volatile("cp.async.cg.shared.global [%0], [%1], 16;" :: "r"(dst), "l"(src));
}
__device__ __forceinline__ uint32_t s2u(const void* p) {
    uint32_t a;
    asm("{ .reg .u64 t; cvta.to.shared.u64 t, %1; cvt.u32.u64 %0, t; }" : "=r"(a) : "l"(p));
    return a;
}
__device__ __forceinline__ uint32_t sw(uint32_t x) { return x ^ ((x >> 3) & 0x70); }
__device__ __forceinline__ void ldsm4(uint32_t* a, uint32_t addr) {
    asm volatile("ldmatrix.sync.aligned.m8n8.x4.shared.b16 {%0,%1,%2,%3}, [%4];"
                 : "=r"(a[0]), "=r"(a[1]), "=r"(a[2]), "=r"(a[3]) : "r"(addr));
}
__device__ __forceinline__ void mma16816(float* c, const uint32_t* a, const uint32_t* b) {
    asm volatile(
        "mma.sync.aligned.m16n8k16.row.col.f32.bf16.bf16.f32 "
        "{%0,%1,%2,%3}, {%4,%5,%6,%7}, {%8,%9}, {%0,%1,%2,%3};"
        : "+f"(c[0]), "+f"(c[1]), "+f"(c[2]), "+f"(c[3])
        : "r"(a[0]), "r"(a[1]), "r"(a[2]), "r"(a[3]), "r"(b[0]), "r"(b[1]));
}

// =================== K1: row-normalize e ===================
__global__ void k_norm_e(const float* __restrict__ emb) {
    int r = blockIdx.x, t = threadIdx.x;   // 512 x 128
    float v[4], s = 0.f;
#pragma unroll
    for (int i = 0; i < 4; i++) { v[i] = emb[r * FEAT + t + i * 128]; s += v[i] * v[i]; }
#pragma unroll
    for (int o = 16; o; o >>= 1) s += __shfl_xor_sync(0xffffffffu, s, o);
    __shared__ float sm[4];
    if ((t & 31) == 0) sm[t >> 5] = s;
    __syncthreads();
    float inv = rsqrtf(sm[0] + sm[1] + sm[2] + sm[3]);
#pragma unroll
    for (int i = 0; i < 4; i++) {
        float x = v[i] * inv;
        g_e[r * FEAT + t + i * 128] = x;
        g_ebf[r * FEAT + t + i * 128] = __float2bfloat16(x);
    }
}

// =================== K2: transpose w -> bf16 [CPAD][512] + invwn ===================
__global__ void k_transpose(const float* __restrict__ w) {
    __shared__ __nv_bfloat16 tile[32][520];
    __shared__ float red[8][32];
    int c0 = blockIdx.x * 32;
    int t = threadIdx.x;
    if (c0 >= NCLS) {  // pad rows: zero fill
        uint32_t* dst = (uint32_t*)&g_wbf[(size_t)c0 * FEAT];
        for (int i = t; i < 32 * 256; i += 256) dst[i] = 0u;
        return;
    }
    int c = t & 31, kp = t >> 5;
    float acc = 0.f;
#pragma unroll 8
    for (int k = kp; k < FEAT; k += 8) {
        float v = w[(size_t)k * NCLS + c0 + c];
        acc += v * v;
        tile[c][k] = __float2bfloat16(v);
    }
    red[kp][c] = acc;
    __syncthreads();
    if (t < 32) {
        float s = 0.f;
#pragma unroll
        for (int i = 0; i < 8; i++) s += red[i][t];
        g_invwn[c0 + t] = rsqrtf(s);
    }
    int wd = t >> 5, ln = t & 31;
    for (int cc = wd; cc < 32; cc += 8) {
        const uint4* src = (const uint4*)&tile[cc][0];
        uint4* dst = (uint4*)&g_wbf[(size_t)(c0 + cc) * FEAT];
        dst[ln] = src[ln];
        dst[ln + 32] = src[ln + 32];
    }
}

// =================== K3: target logits (fp32 path), one warp per row ===================
__global__ void k_target(const float* __restrict__ w, const int* __restrict__ label) {
    int gw = (blockIdx.x * blockDim.x + threadIdx.x) >> 5;  // 64 blocks x 256 -> 512 warps
    int lane = threadIdx.x & 31;
    if (gw >= NROW) return;
    int lab = label[gw];
    const float* e = g_e + gw * FEAT;
    float dot = 0.f;
#pragma unroll
    for (int j = 0; j < 16; j++) {
        int k = lane + 32 * j;
        dot += e[k] * w[(size_t)k * NCLS + lab];
    }
#pragma unroll
    for (int o = 16; o; o >>= 1) dot += __shfl_xor_sync(0xffffffffu, dot, o);
    if (lane == 0)
        g_tl[gw] = fminf(1.0f, fmaxf(-1.0f, dot * g_invwn[lab]));
}

// =================== K3b: ctm/ft/t from target logits ===================
__global__ void k_prep() {
    int i = threadIdx.x;  // 512
    float tl = g_tl[i];
    float sint = sqrtf(fmaxf(0.f, 1.0f - tl * tl));
    float ctm = tl * C_COS_M - sint * C_SIN_M;
    g_ctm[i] = ctm;
    g_ft[i] = (tl > C_THRESH) ? ctm : (tl - C_MM);
    float s = tl;
#pragma unroll
    for (int o = 16; o; o >>= 1) s += __shfl_xor_sync(0xffffffffu, s, o);
    __shared__ float sm[16];
    if ((i & 31) == 0) sm[i >> 5] = s;
    __syncthreads();
    if (i < 16) {
        float v = sm[i];
#pragma unroll
        for (int o = 8; o; o >>= 1) v += __shfl_xor_sync(0x0000ffffu, v, o);
        if (i == 0) g_t = 0.01f * (v / (float)NROW);
    }
}

// =================== K4: bf16 mma.sync GEMM + fused epilogue ===================
// dynamic smem: stage0 A @0 (16KB), B @16K; stage1 A @32K, B @48K  => 64KB
#define SMSZ 65536

__device__ __forceinline__ void load_chunk(uint32_t sb, int s, int chunk,
                                           const char* ag0, const char* bg0, int tid) {
    const char* ag = ag0 + chunk * 128;
    const char* bg = bg0 + chunk * 128;
    uint32_t as_ = sb + s * 32768;
    uint32_t bs_ = as_ + 16384;
#pragma unroll
    for (int u = 0; u < 4; u++) {          // A: 128 rows x 8 segs
        int i = tid + u * 256;
        int row = i >> 3, seg = i & 7;
        cp16(as_ + sw((uint32_t)(row * 128 + seg * 16)), ag + (size_t)row * 1024 + seg * 16);
    }
#pragma unroll
    for (int u = 0; u < 4; u++) {          // B: 128 rows x 8 segs
        int i = tid + u * 256;
        int row = i >> 3, seg = i & 7;
        cp16(bs_ + sw((uint32_t)(row * 128 + seg * 16)), bg + (size_t)row * 1024 + seg * 16);
    }
}

__global__ void __launch_bounds__(256, 2) k_gemm(const int* __restrict__ label) {
    extern __shared__ char smdy[];
    uint32_t sb = s2u(smdy);
    const int tid = threadIdx.x, lane = tid & 31, wid = tid >> 5;
    const int warpM = wid >> 2;            // 0..1
    const int warpN = wid & 3;             // 0..3
    const int r0 = blockIdx.x * BM;
    const int c0 = blockIdx.y * BN;

    float acc[4][4][4];
#pragma unroll
    for (int a = 0; a < 4; a++)
#pragma unroll
        for (int b = 0; b < 4; b++)
#pragma unroll
            for (int c = 0; c < 4; c++) acc[a][b][c] = 0.f;

    const char* ag0 = (const char*)(g_ebf + (size_t)r0 * FEAT);
    const char* bg0 = (const char*)(g_wbf + (size_t)c0 * FEAT);

    load_chunk(sb, 0, 0, ag0, bg0, tid);
    asm volatile("cp.async.commit_group;");

#pragma unroll 1
    for (int it = 0; it < NCH; it++) {
        int s = it & 1;
        if (it < NCH - 1) {
            load_chunk(sb, s ^ 1, it + 1, ag0, bg0, tid);
            asm volatile("cp.async.commit_group;");
            asm volatile("cp.async.wait_group 1;");
        } else {
            asm volatile("cp.async.wait_group 0;");
        }
        __syncthreads();

        uint32_t aST = sb + s * 32768;
        uint32_t bST = aST + 16384;
#pragma unroll
        for (int ks = 0; ks < 4; ks++) {
            int kb = ks * 32;
            uint32_t af[4][4], bf[2][4];
#pragma unroll
            for (int mt = 0; mt < 4; mt++) {
                int r = warpM * 64 + mt * 16 + (lane & 7) + ((lane >> 3) & 1) * 8;
                int kb2 = kb + ((lane >> 4) & 1) * 16;
                ldsm4(af[mt], aST + sw((uint32_t)(r * 128 + kb2)));
            }
#pragma unroll
            for (int pr = 0; pr < 2; pr++) {
                int r = warpN * 32 + pr * 16 + ((lane >> 4) & 1) * 8 + (lane & 7);
                int kb2 = kb + ((lane >> 3) & 1) * 16;
                ldsm4(bf[pr], bST + sw((uint32_t)(r * 128 + kb2)));
            }
#pragma unroll
            for (int mt = 0; mt < 4; mt++)
#pragma unroll
                for (int nt = 0; nt < 4; nt++)
                    mma16816(acc[mt][nt], af[mt], &bf[nt >> 1][(nt & 1) * 2]);
        }
        __syncthreads();   // all reads of this stage done before it's overwritten
    }

    // ---- epilogue ----
    float* smf = (float*)smdy;
    int*   smi = (int*)smdy;
    // [0..127] invwn, [128..255] ctm, [256..383] ft, [384..511] label,
    // [512..1023] pm[4][128], [1024..1535] ps, [1536..2047] psl
    if (tid < 128) {
        int c = c0 + tid;
        smf[tid] = (c < NCLS) ? g_invwn[c] : 0.f;
        int r = r0 + tid;
        smf[128 + tid] = g_ctm[r];
        smf[256 + tid] = g_ft[r];
        smi[384 + tid] = label[r];
    }
    __syncthreads();

    const float tad = g_t;
    const int g = lane >> 2, q = lane & 3;
#pragma unroll
    for (int mt = 0; mt < 4; mt++) {
#pragma unroll
        for (int half = 0; half < 2; half++) {
            int rl = warpM * 64 + mt * 16 + g + half * 8;
            float ctm = smf[128 + rl], ft = smf[256 + rl];
            int lab = smi[384 + rl];
            float L[8];
            float mx = -3.0e38f;
#pragma unroll
            for (int nt = 0; nt < 4; nt++) {
#pragma unroll
                for (int b = 0; b < 2; b++) {
                    int cl = warpN * 32 + nt * 8 + q * 2 + b;
                    int c = c0 + cl;
                    float Lv;
                    if (c < NCLS) {
                        float cv = acc[mt][nt][half * 2 + b] * smf[cl];
                        cv = fminf(1.f, fmaxf(-1.f, cv));
                        if (c == lab) {
                            Lv = C_S * ft;
                        } else {
                            if (cv > ctm) cv = cv * (tad + cv);
                            Lv = C_S * cv;
                        }
                        mx = fmaxf(mx, Lv);
                    } else {
                        Lv = -3.0e38f;
                    }
                    L[nt * 2 + b] = Lv;
                }
            }
            mx = fmaxf(mx, __shfl_xor_sync(0xffffffffu, mx, 1));
            mx = fmaxf(mx, __shfl_xor_sync(0xffffffffu, mx, 2));
            float s = 0.f, sl = 0.f;
#pragma unroll
            for (int j = 0; j < 8; j++) {
                if (L[j] > -1.0e38f) { s += __expf(L[j] - mx); sl += L[j]; }
            }
            s  += __shfl_xor_sync(0xffffffffu, s, 1);
            s  += __shfl_xor_sync(0xffffffffu, s, 2);
            sl += __shfl_xor_sync(0xffffffffu, sl, 1);
            sl += __shfl_xor_sync(0xffffffffu, sl, 2);
            if (q == 0) {
                smf[512  + warpN * 128 + rl] = mx;
                smf[1024 + warpN * 128 + rl] = s;
                smf[1536 + warpN * 128 + rl] = sl;
            }
        }
    }
    __syncthreads();

    if (tid < 128) {
        float m = -3.0e38f;
#pragma unroll
        for (int wn = 0; wn < 4; wn++) m = fmaxf(m, smf[512 + wn * 128 + tid]);
        float s = 0.f, sl = 0.f;
#pragma unroll
        for (int wn = 0; wn < 4; wn++) {
            float mw = smf[512 + wn * 128 + tid];
            if (mw > -1.0e38f) s += smf[1024 + wn * 128 + tid] * __expf(mw - m);
            sl += smf[1536 + wn * 128 + tid];
        }
        int slot = (r0 + tid) * CTP + blockIdx.y;
        g_pm[slot] = m;
        g_ps[slot] = s;
        g_psl[slot] = sl;
    }
}

// =================== K5: merge partials per row ===================
__global__ void k_rowreduce() {
    int r = blockIdx.x;
    int tid = threadIdx.x;  // 256
    float m = -3.0e38f, s = 0.f, sl = 0.f;
    for (int ct = tid; ct < CTP; ct += 256) {
        float m2 = g_pm[r * CTP + ct];
        float s2 = g_ps[r * CTP + ct];
        sl += g_psl[r * CTP + ct];
        if (m2 > m) { s = s * __expf(m - m2) + s2; m = m2; }
        else        { s += s2 * __expf(m2 - m); }
    }
    __shared__ float sm_m[256], sm_s[256], sm_sl[256];
    sm_m[tid] = m; sm_s[tid] = s; sm_sl[tid] = sl;
    __syncthreads();
    for (int o = 128; o; o >>= 1) {
        if (tid < o) {
            float m1 = sm_m[tid], s1 = sm_s[tid];
            float m2 = sm_m[tid + o], s2 = sm_s[tid + o];
            float M = fmaxf(m1, m2);
            sm_s[tid] = s1 * __expf(m1 - M) + s2 * __expf(m2 - M);
            sm_m[tid] = M;
            sm_sl[tid] += sm_sl[tid + o];
        }
        __syncthreads();
    }
    if (tid == 0) {
        float LSE = sm_m[0] + logf(sm_s[0]);
        float nll = LSE - C_S * g_ft[r];
        float smooth = LSE - sm_sl[0] / (float)NCLS;
        g_rowloss[r] = (1.0f - C_EPS) * nll + C_EPS * smooth;
    }
}

// =================== K6: mean ===================
__global__ void k_final(float* __restrict__ out) {
    int tid = threadIdx.x;  // 512
    float v = g_rowloss[tid];
#pragma unroll
    for (int o = 16; o; o >>= 1) v += __shfl_xor_sync(0xffffffffu, v, o);
    __shared__ float sm[16];
    if ((tid & 31) == 0) sm[tid >> 5] = v;
    __syncthreads();
    if (tid < 16) {
        float x = sm[tid];
#pragma unroll
        for (int o = 8; o; o >>= 1) x += __shfl_xor_sync(0x0000ffffu, x, o);
        if (tid == 0) out[0] = x / (float)NROW;
    }
}

// ===================================================
extern "C" void kernel_launch(void* const* d_in, const int* in_sizes, int n_in,
                              void* d_out, int out_size) {
    const float* emb = (const float*)d_in[0];
    const float* w = (const float*)d_in[1];
    const int* label = (const int*)d_in[2];
    float* out = (float*)d_out;

    cudaFuncSetAttribute(k_gemm, cudaFuncAttributeMaxDynamicSharedMemorySize, SMSZ);

    k_norm_e<<<NROW, 128>>>(emb);
    k_transpose<<<3128, 256>>>(w);
    k_target<<<64, 256>>>(w, label);
    k_prep<<<1, NROW>>>();
    k_gemm<<<dim3(NRT, NCT), 256, SMSZ>>>(label);
    k_rowreduce<<<NROW, 256>>>();
    k_final<<<1, NROW>>>(out);
}